// round 8
// baseline (speedup 1.0000x reference)
#include <cuda_runtime.h>
#include <math.h>

#define NI   128
#define Hh   400
#define Ww   400
#define MS   28
#define CT   80
#define CS   53
#define HW   (Hh*Ww)          // 160000
#define HW4  (HW/4)           // 40000
#define NCH  (CS + NI)        // 181
#define HG   1600
#define IGNORE_LBL 255

#define PIX_PER_BLK 32
#define NGRP 8
#define TPB  256
#define NBLK (HW4 / PIX_PER_BLK)   // 1250

__device__ float g_partial[NBLK];
__device__ float g_count[NBLK];
__device__ unsigned int g_ctr = 0;

__global__ __launch_bounds__(TPB)
void fused_kernel(const float* __restrict__ mask_logits,   // [N,CT,MS,MS]
                  const float* __restrict__ stuff_logit,   // [CS,H,W]
                  const float* __restrict__ thing_logit,   // [CT,H,W]
                  const float* __restrict__ bbox,          // [N,4]
                  const int*   __restrict__ cls_idx,       // [N]
                  const int*   __restrict__ gt,            // [HG,WG]
                  float* __restrict__ out,                 // pan_logit
                  float* __restrict__ loss_out)
{
    __shared__ int   s_x0[NI], s_x2[NI], s_y0[NI], s_y2[NI];
    __shared__ int   s_cx1[NI], s_cx2[NI], s_cy1[NI], s_cy2[NI];
    __shared__ float s_sy[NI], s_sx[NI];
    __shared__ int   s_cls[NI];
    __shared__ short s_list[NI];
    __shared__ unsigned s_bal[4];
    __shared__ int   s_off[4];
    __shared__ int   s_cnt;
    __shared__ float4 s_part[TPB];

    const int tid  = threadIdx.x;
    const int pix  = tid & (PIX_PER_BLK - 1);
    const int grp  = tid >> 5;
    const int lane = tid & 31;
    const int wrp  = tid >> 5;

    // block pixel span: [p0, p0 + 128)
    const int p0 = blockIdx.x * PIX_PER_BLK * 4;
    const int by0 = p0 / Ww;
    const int by1 = (p0 + PIX_PER_BLK * 4 - 1) / Ww;
    int bxs, bxe;
    if (by0 == by1) { bxs = p0 - by0 * Ww; bxe = bxs + PIX_PER_BLK * 4 - 1; }
    else            { bxs = 0;             bxe = Ww - 1; }   // conservative

    // -------- instance rect prep + block-level overlap flag ------------------
    bool flag = false;
    if (tid < NI) {
        const int n = tid;
        const float4 bb = ((const float4*)bbox)[n];
        const int x0b = (int)floorf(bb.x * 0.25f);
        const int y0b = (int)floorf(bb.y * 0.25f);
        const int x2b = (int)floorf(bb.z * 0.25f);
        const int y2b = (int)floorf(bb.w * 0.25f);
        s_x0[n] = x0b; s_y0[n] = y0b; s_x2[n] = x2b; s_y2[n] = y2b;
        s_sy[n] = (float)MS / (float)(y2b - y0b + 1);
        s_sx[n] = (float)MS / (float)(x2b - x0b + 1);
        const int cx1 = (int)(bb.x * 0.25f);
        const int cy1 = (int)(bb.y * 0.25f);
        const int cx2 = (int)(rintf(bb.z * 0.25f) + 1.0f);
        const int cy2 = (int)(rintf(bb.w * 0.25f) + 1.0f);
        s_cx1[n] = cx1; s_cy1[n] = cy1; s_cx2[n] = cx2; s_cy2[n] = cy2;
        s_cls[n] = cls_idx[n];

        const int rx0 = min(x0b, cx1);
        const int ry0 = min(y0b, cy1);
        const int rx1 = max(x2b, cx2 - 1);
        const int ry1 = max(y2b, cy2 - 1);
        flag = (ry0 <= by1) && (ry1 >= by0) && (rx0 <= bxe) && (rx1 >= bxs);
    }
    const unsigned bal = __ballot_sync(0xffffffffu, flag);
    if (lane == 0 && wrp < 4) s_bal[wrp] = bal;
    __syncthreads();
    if (tid == 0) {
        int off = 0;
        #pragma unroll
        for (int w = 0; w < 4; ++w) { s_off[w] = off; off += __popc(s_bal[w]); }
        s_cnt = off;
    }
    __syncthreads();
    if (flag)
        s_list[s_off[wrp] + __popc(bal & ((1u << lane) - 1u))] = (short)tid;
    __syncthreads();

    // -------- per-(pixel, channel-group) work --------------------------------
    const int qi = blockIdx.x * PIX_PER_BLK + pix;
    const int p  = qi * 4;
    const int y  = p / Ww;
    const int x  = p - y * Ww;

    const int c_lo = (grp * NCH) / NGRP;
    const int c_hi = ((grp + 1) * NCH) / NGRP;

    const float4* sp4 = (const float4*)stuff_logit + qi;
    float4*       op4 = (float4*)out + qi;

    float s0 = 0.f, s1 = 0.f, s2 = 0.f, s3 = 0.f;

    // stuff channels in my group: copy + exp
    const int cs_end = min(c_hi, CS);
    #pragma unroll 4
    for (int c = c_lo; c < cs_end; ++c) {
        const float4 v = sp4[(size_t)c * HW4];
        op4[(size_t)c * HW4] = v;
        s0 += __expf(v.x); s1 += __expf(v.y);
        s2 += __expf(v.z); s3 += __expf(v.w);
    }

    // thing channels in my group: tight zero fill + baseline ones
    const int ct_begin = max(c_lo, CS);
    const float4 z4 = make_float4(0.f, 0.f, 0.f, 0.f);
    #pragma unroll 4
    for (int c = ct_begin; c < c_hi; ++c)
        op4[(size_t)c * HW4] = z4;
    {
        const float ones = (float)max(0, c_hi - ct_begin);   // FIX: clamp at 0
        s0 += ones; s1 += ones; s2 += ones; s3 += ones;
    }

    // overwrite block-covering instances that fall in my group
    const int m = s_cnt;
    const int n_lo = ct_begin - CS;
    const int n_hi = c_hi - CS;
    for (int k = 0; k < m; ++k) {
        const int n = s_list[k];
        if (n < n_lo || n >= n_hi) continue;

        const int x0b = s_x0[n], x2b = s_x2[n];
        const int y0b = s_y0[n], y2b = s_y2[n];
        const int cx1 = s_cx1[n], cx2 = s_cx2[n];
        const int cy1 = s_cy1[n], cy2 = s_cy2[n];

        const bool yin_m = (y >= y0b) && (y <= y2b);
        const bool yin_s = (y >= cy1) && (y <  cy2);
        const bool xov_m = yin_m && (x + 3 >= x0b) && (x <= x2b);
        const bool xov_s = yin_s && (x + 3 >= cx1) && (x <  cx2);
        if (!(xov_m || xov_s)) continue;

        const int cls = s_cls[n];
        float ty = 0.f; int i0 = 0, i1 = 0;
        const float* ml = mask_logits + ((size_t)n * CT + cls) * (MS * MS);
        if (xov_m) {
            const float sy = ((float)(y - y0b) + 0.5f) * s_sy[n] - 0.5f;
            const float fy = floorf(sy);
            ty = sy - fy;
            i0 = min(max((int)fy, 0), MS - 1);
            i1 = min(max((int)fy + 1, 0), MS - 1);
        }
        const float* tl = thing_logit + (size_t)cls * HW + p;

        float v[4];
        #pragma unroll
        for (int j = 0; j < 4; ++j) {
            const int xx = x + j;
            float vv = 0.0f;
            if (yin_m && xx >= x0b && xx <= x2b) {
                const float sx = ((float)(xx - x0b) + 0.5f) * s_sx[n] - 0.5f;
                const float fx = floorf(sx);
                const float tx = sx - fx;
                const int j0 = min(max((int)fx, 0), MS - 1);
                const int j1 = min(max((int)fx + 1, 0), MS - 1);
                const float r00 = ml[i0 * MS + j0];
                const float r10 = ml[i1 * MS + j0];
                const float r01 = ml[i0 * MS + j1];
                const float r11 = ml[i1 * MS + j1];
                const float c0 = r00 * (1.0f - ty) + r10 * ty;
                const float c1 = r01 * (1.0f - ty) + r11 * ty;
                vv = c0 * (1.0f - tx) + c1 * tx;
            }
            if (yin_s && xx >= cx1 && xx < cx2) vv += tl[j];
            v[j] = vv;
        }
        s0 += __expf(v[0]) - 1.0f;
        s1 += __expf(v[1]) - 1.0f;
        s2 += __expf(v[2]) - 1.0f;
        s3 += __expf(v[3]) - 1.0f;
        op4[(size_t)(n + CS) * HW4] = make_float4(v[0], v[1], v[2], v[3]);
    }

    // -------- combine NGRP partials per pixel --------------------------------
    s_part[tid] = make_float4(s0, s1, s2, s3);
    __syncthreads();   // block-scope visibility of all this block's stores

    float contrib = 0.0f, cnt = 0.0f;

    if (grp == 0) {
        float t0s = 0.f, t1s = 0.f, t2s = 0.f, t3s = 0.f;
        #pragma unroll
        for (int g = 0; g < NGRP; ++g) {
            const float4 pp = s_part[pix + g * PIX_PER_BLK];
            t0s += pp.x; t1s += pp.y; t2s += pp.z; t3s += pp.w;
        }

        const int* gr = gt + (size_t)(y * 4) * HG + (size_t)x * 4;
        const int g0 = gr[0], g1 = gr[4], g2 = gr[8], g3 = gr[12];

        const int t0 = min(max(g0, 0), NCH - 1);
        const int t1 = min(max(g1, 0), NCH - 1);
        const int t2 = min(max(g2, 0), NCH - 1);
        const int t3 = min(max(g3, 0), NCH - 1);
        const float tv0 = out[(size_t)t0 * HW + p + 0];
        const float tv1 = out[(size_t)t1 * HW + p + 1];
        const float tv2 = out[(size_t)t2 * HW + p + 2];
        const float tv3 = out[(size_t)t3 * HW + p + 3];

        if (g0 != IGNORE_LBL) { contrib += __logf(t0s) - tv0; cnt += 1.f; }
        if (g1 != IGNORE_LBL) { contrib += __logf(t1s) - tv1; cnt += 1.f; }
        if (g2 != IGNORE_LBL) { contrib += __logf(t2s) - tv2; cnt += 1.f; }
        if (g3 != IGNORE_LBL) { contrib += __logf(t3s) - tv3; cnt += 1.f; }
    }
    __syncthreads();

    // -------- deterministic block reduction ----------------------------------
    __shared__ float ssum[TPB];
    __shared__ float scnt[TPB];
    ssum[tid] = contrib;
    scnt[tid] = cnt;
    __syncthreads();
    #pragma unroll
    for (int off = 128; off > 0; off >>= 1) {
        if (tid < off) { ssum[tid] += ssum[tid + off]; scnt[tid] += scnt[tid + off]; }
        __syncthreads();
    }

    __shared__ bool is_last;
    if (tid == 0) {
        g_partial[blockIdx.x] = ssum[0];
        g_count[blockIdx.x]   = scnt[0];
        __threadfence();
        const unsigned old = atomicAdd(&g_ctr, 1u);
        is_last = (old == NBLK - 1);
        if (is_last) g_ctr = 0;          // reset for graph replay
    }
    __syncthreads();

    if (is_last) {
        __shared__ double sd[TPB];
        __shared__ double sc[TPB];
        double s = 0.0, c = 0.0;
        for (int i = tid; i < NBLK; i += TPB) {
            s += (double)g_partial[i];
            c += (double)g_count[i];
        }
        sd[tid] = s; sc[tid] = c;
        __syncthreads();
        #pragma unroll
        for (int off = 128; off > 0; off >>= 1) {
            if (tid < off) { sd[tid] += sd[tid + off]; sc[tid] += sc[tid + off]; }
            __syncthreads();
        }
        if (tid == 0) *loss_out = (float)(sd[0] / fmax(sc[0], 1.0));
    }
}

// ---------------------------------------------------------------------------
extern "C" void kernel_launch(void* const* d_in, const int* in_sizes, int n_in,
                              void* d_out, int out_size)
{
    const float* mask_logits = (const float*)d_in[0];
    const float* stuff_logit = (const float*)d_in[1];
    const float* thing_logit = (const float*)d_in[2];
    const float* bbox        = (const float*)d_in[3];
    const int*   cls_idx     = (const int*)  d_in[4];
    const int*   gt          = (const int*)  d_in[5];

    float* out = (float*)d_out;

    fused_kernel<<<NBLK, TPB>>>(mask_logits, stuff_logit, thing_logit,
                                bbox, cls_idx, gt, out,
                                out + (size_t)out_size - 1);
}

// round 9
// speedup vs baseline: 1.0266x; 1.0266x over previous
#include <cuda_runtime.h>
#include <math.h>

#define NI   128
#define Hh   400
#define Ww   400
#define MS   28
#define CT   80
#define CS   53
#define HW   (Hh*Ww)          // 160000
#define HW4  (HW/4)           // 40000
#define NCH  (CS + NI)        // 181
#define HG   1600
#define IGNORE_LBL 255

#define PIX_PER_BLK 64
#define NGRP 4
#define TPB  256
#define NBLK (HW4 / PIX_PER_BLK)   // 625

__device__ float g_partial[NBLK];
__device__ float g_count[NBLK];
__device__ unsigned int g_ctr = 0;

__global__ __launch_bounds__(TPB)
void fused_kernel(const float* __restrict__ mask_logits,   // [N,CT,MS,MS]
                  const float* __restrict__ stuff_logit,   // [CS,H,W]
                  const float* __restrict__ thing_logit,   // [CT,H,W]
                  const float* __restrict__ bbox,          // [N,4]
                  const int*   __restrict__ cls_idx,       // [N]
                  const int*   __restrict__ gt,            // [HG,WG]
                  float* __restrict__ out,                 // pan_logit
                  float* __restrict__ loss_out)
{
    __shared__ int   s_x0[NI], s_x2[NI], s_y0[NI], s_y2[NI];
    __shared__ int   s_cx1[NI], s_cx2[NI], s_cy1[NI], s_cy2[NI];
    __shared__ float s_sy[NI], s_sx[NI];
    __shared__ int   s_cls[NI];
    __shared__ short s_list[NI];
    __shared__ unsigned s_bal[4];
    __shared__ int   s_off[4];
    __shared__ int   s_cnt;
    __shared__ float4 s_part[TPB];

    const int tid  = threadIdx.x;
    const int pix  = tid & (PIX_PER_BLK - 1);
    const int grp  = tid >> 6;            // 0..3
    const int lane = tid & 31;
    const int wrp  = tid >> 5;

    // block pixel span: [p0, p0 + 256)
    const int p0 = blockIdx.x * PIX_PER_BLK * 4;
    const int by0 = p0 / Ww;
    const int by1 = (p0 + PIX_PER_BLK * 4 - 1) / Ww;
    int bxs, bxe;
    if (by0 == by1) { bxs = p0 - by0 * Ww; bxe = bxs + PIX_PER_BLK * 4 - 1; }
    else            { bxs = 0;             bxe = Ww - 1; }   // conservative

    // -------- instance rect prep + block-level overlap flag ------------------
    bool flag = false;
    if (tid < NI) {
        const int n = tid;
        const float4 bb = ((const float4*)bbox)[n];
        const int x0b = (int)floorf(bb.x * 0.25f);
        const int y0b = (int)floorf(bb.y * 0.25f);
        const int x2b = (int)floorf(bb.z * 0.25f);
        const int y2b = (int)floorf(bb.w * 0.25f);
        s_x0[n] = x0b; s_y0[n] = y0b; s_x2[n] = x2b; s_y2[n] = y2b;
        s_sy[n] = (float)MS / (float)(y2b - y0b + 1);
        s_sx[n] = (float)MS / (float)(x2b - x0b + 1);
        const int cx1 = (int)(bb.x * 0.25f);
        const int cy1 = (int)(bb.y * 0.25f);
        const int cx2 = (int)(rintf(bb.z * 0.25f) + 1.0f);
        const int cy2 = (int)(rintf(bb.w * 0.25f) + 1.0f);
        s_cx1[n] = cx1; s_cy1[n] = cy1; s_cx2[n] = cx2; s_cy2[n] = cy2;
        s_cls[n] = cls_idx[n];

        const int rx0 = min(x0b, cx1);
        const int ry0 = min(y0b, cy1);
        const int rx1 = max(x2b, cx2 - 1);
        const int ry1 = max(y2b, cy2 - 1);
        flag = (ry0 <= by1) && (ry1 >= by0) && (rx0 <= bxe) && (rx1 >= bxs);
    }
    const unsigned bal = __ballot_sync(0xffffffffu, flag);
    if (lane == 0 && wrp < 4) s_bal[wrp] = bal;
    __syncthreads();
    if (tid == 0) {
        int off = 0;
        #pragma unroll
        for (int w = 0; w < 4; ++w) { s_off[w] = off; off += __popc(s_bal[w]); }
        s_cnt = off;
    }
    __syncthreads();
    if (flag)
        s_list[s_off[wrp] + __popc(bal & ((1u << lane) - 1u))] = (short)tid;
    __syncthreads();

    // -------- per-(pixel, channel-group) work --------------------------------
    const int qi = blockIdx.x * PIX_PER_BLK + pix;
    const int p  = qi * 4;
    const int y  = p / Ww;
    const int x  = p - y * Ww;

    const float4* sp4 = (const float4*)stuff_logit + qi;
    float4*       op4 = (float4*)out + qi;

    float s0 = 0.f, s1 = 0.f, s2 = 0.f, s3 = 0.f;

    // stuff channels (round-robin c = grp, grp+4, ... < CS): copy + exp
    #pragma unroll 4
    for (int c = grp; c < CS; c += NGRP) {
        const float4 v = sp4[(size_t)c * HW4];
        op4[(size_t)c * HW4] = v;
        s0 += __expf(v.x); s1 += __expf(v.y);
        s2 += __expf(v.z); s3 += __expf(v.w);
    }

    // thing channels in my group (round-robin): tight zero fill + baseline ones
    // first thing channel >= CS with c % NGRP == grp
    const int ct_first = CS + ((grp - (CS % NGRP) + NGRP) % NGRP);
    const float4 z4 = make_float4(0.f, 0.f, 0.f, 0.f);
    #pragma unroll 4
    for (int c = ct_first; c < NCH; c += NGRP)
        op4[(size_t)c * HW4] = z4;
    {
        const float ones = (float)((NCH - ct_first + NGRP - 1) / NGRP);  // = 32
        s0 += ones; s1 += ones; s2 += ones; s3 += ones;
    }

    // overwrite block-covering instances whose channel falls in my group
    const int m = s_cnt;
    for (int k = 0; k < m; ++k) {
        const int n = s_list[k];
        if (((n + CS) & (NGRP - 1)) != grp) continue;

        const int x0b = s_x0[n], x2b = s_x2[n];
        const int y0b = s_y0[n], y2b = s_y2[n];
        const int cx1 = s_cx1[n], cx2 = s_cx2[n];
        const int cy1 = s_cy1[n], cy2 = s_cy2[n];

        const bool yin_m = (y >= y0b) && (y <= y2b);
        const bool yin_s = (y >= cy1) && (y <  cy2);
        const bool xov_m = yin_m && (x + 3 >= x0b) && (x <= x2b);
        const bool xov_s = yin_s && (x + 3 >= cx1) && (x <  cx2);
        if (!(xov_m || xov_s)) continue;

        const int cls = s_cls[n];
        float ty = 0.f; int i0 = 0, i1 = 0;
        const float* ml = mask_logits + ((size_t)n * CT + cls) * (MS * MS);
        if (xov_m) {
            const float sy = ((float)(y - y0b) + 0.5f) * s_sy[n] - 0.5f;
            const float fy = floorf(sy);
            ty = sy - fy;
            i0 = min(max((int)fy, 0), MS - 1);
            i1 = min(max((int)fy + 1, 0), MS - 1);
        }
        const float* tl = thing_logit + (size_t)cls * HW + p;

        float v[4];
        #pragma unroll
        for (int j = 0; j < 4; ++j) {
            const int xx = x + j;
            float vv = 0.0f;
            if (yin_m && xx >= x0b && xx <= x2b) {
                const float sx = ((float)(xx - x0b) + 0.5f) * s_sx[n] - 0.5f;
                const float fx = floorf(sx);
                const float tx = sx - fx;
                const int j0 = min(max((int)fx, 0), MS - 1);
                const int j1 = min(max((int)fx + 1, 0), MS - 1);
                const float r00 = ml[i0 * MS + j0];
                const float r10 = ml[i1 * MS + j0];
                const float r01 = ml[i0 * MS + j1];
                const float r11 = ml[i1 * MS + j1];
                const float c0 = r00 * (1.0f - ty) + r10 * ty;
                const float c1 = r01 * (1.0f - ty) + r11 * ty;
                vv = c0 * (1.0f - tx) + c1 * tx;
            }
            if (yin_s && xx >= cx1 && xx < cx2) vv += tl[j];
            v[j] = vv;
        }
        s0 += __expf(v[0]) - 1.0f;
        s1 += __expf(v[1]) - 1.0f;
        s2 += __expf(v[2]) - 1.0f;
        s3 += __expf(v[3]) - 1.0f;
        op4[(size_t)(n + CS) * HW4] = make_float4(v[0], v[1], v[2], v[3]);
    }

    // -------- combine NGRP partials per pixel --------------------------------
    s_part[tid] = make_float4(s0, s1, s2, s3);
    __syncthreads();   // block-scope visibility of all this block's stores

    float contrib = 0.0f, cnt = 0.0f;

    if (grp == 0) {
        float t0s = 0.f, t1s = 0.f, t2s = 0.f, t3s = 0.f;
        #pragma unroll
        for (int g = 0; g < NGRP; ++g) {
            const float4 pp = s_part[pix + g * PIX_PER_BLK];
            t0s += pp.x; t1s += pp.y; t2s += pp.z; t3s += pp.w;
        }

        const int* gr = gt + (size_t)(y * 4) * HG + (size_t)x * 4;
        const int g0 = gr[0], g1 = gr[4], g2 = gr[8], g3 = gr[12];

        const int t0 = min(max(g0, 0), NCH - 1);
        const int t1 = min(max(g1, 0), NCH - 1);
        const int t2 = min(max(g2, 0), NCH - 1);
        const int t3 = min(max(g3, 0), NCH - 1);
        const float tv0 = out[(size_t)t0 * HW + p + 0];
        const float tv1 = out[(size_t)t1 * HW + p + 1];
        const float tv2 = out[(size_t)t2 * HW + p + 2];
        const float tv3 = out[(size_t)t3 * HW + p + 3];

        if (g0 != IGNORE_LBL) { contrib += __logf(t0s) - tv0; cnt += 1.f; }
        if (g1 != IGNORE_LBL) { contrib += __logf(t1s) - tv1; cnt += 1.f; }
        if (g2 != IGNORE_LBL) { contrib += __logf(t2s) - tv2; cnt += 1.f; }
        if (g3 != IGNORE_LBL) { contrib += __logf(t3s) - tv3; cnt += 1.f; }
    }
    __syncthreads();

    // -------- deterministic block reduction ----------------------------------
    __shared__ float ssum[TPB];
    __shared__ float scnt[TPB];
    ssum[tid] = contrib;
    scnt[tid] = cnt;
    __syncthreads();
    #pragma unroll
    for (int off = 128; off > 0; off >>= 1) {
        if (tid < off) { ssum[tid] += ssum[tid + off]; scnt[tid] += scnt[tid + off]; }
        __syncthreads();
    }

    __shared__ bool is_last;
    if (tid == 0) {
        g_partial[blockIdx.x] = ssum[0];
        g_count[blockIdx.x]   = scnt[0];
        __threadfence();
        const unsigned old = atomicAdd(&g_ctr, 1u);
        is_last = (old == NBLK - 1);
        if (is_last) g_ctr = 0;          // reset for graph replay
    }
    __syncthreads();

    if (is_last) {
        __shared__ double sd[TPB];
        __shared__ double sc[TPB];
        double s = 0.0, c = 0.0;
        for (int i = tid; i < NBLK; i += TPB) {
            s += (double)g_partial[i];
            c += (double)g_count[i];
        }
        sd[tid] = s; sc[tid] = c;
        __syncthreads();
        #pragma unroll
        for (int off = 128; off > 0; off >>= 1) {
            if (tid < off) { sd[tid] += sd[tid + off]; sc[tid] += sc[tid + off]; }
            __syncthreads();
        }
        if (tid == 0) *loss_out = (float)(sd[0] / fmax(sc[0], 1.0));
    }
}

// ---------------------------------------------------------------------------
extern "C" void kernel_launch(void* const* d_in, const int* in_sizes, int n_in,
                              void* d_out, int out_size)
{
    const float* mask_logits = (const float*)d_in[0];
    const float* stuff_logit = (const float*)d_in[1];
    const float* thing_logit = (const float*)d_in[2];
    const float* bbox        = (const float*)d_in[3];
    const int*   cls_idx     = (const int*)  d_in[4];
    const int*   gt          = (const int*)  d_in[5];

    float* out = (float*)d_out;

    fused_kernel<<<NBLK, TPB>>>(mask_logits, stuff_logit, thing_logit,
                                bbox, cls_idx, gt, out,
                                out + (size_t)out_size - 1);
}

// round 10
// speedup vs baseline: 1.0779x; 1.0500x over previous
#include <cuda_runtime.h>
#include <math.h>

#define NI   128
#define Hh   400
#define Ww   400
#define MS   28
#define CT   80
#define CS   53
#define HW   (Hh*Ww)          // 160000
#define HW4  (HW/4)           // 40000
#define NCH  (CS + NI)        // 181
#define HG   1600
#define IGNORE_LBL 255

#define PIX_PER_BLK 64
#define NGRP 8
#define TPB  512
#define NBLK (HW4 / PIX_PER_BLK)   // 625
#define NWARP (TPB/32)             // 16

__device__ float g_partial[NBLK];
__device__ float g_count[NBLK];
__device__ unsigned int g_ctr = 0;

__global__ __launch_bounds__(TPB)
void fused_kernel(const float* __restrict__ mask_logits,   // [N,CT,MS,MS]
                  const float* __restrict__ stuff_logit,   // [CS,H,W]
                  const float* __restrict__ thing_logit,   // [CT,H,W]
                  const float* __restrict__ bbox,          // [N,4]
                  const int*   __restrict__ cls_idx,       // [N]
                  const int*   __restrict__ gt,            // [HG,WG]
                  float* __restrict__ out,                 // pan_logit
                  float* __restrict__ loss_out)
{
    __shared__ int   s_x0[NI], s_x2[NI], s_y0[NI], s_y2[NI];
    __shared__ int   s_cx1[NI], s_cx2[NI], s_cy1[NI], s_cy2[NI];
    __shared__ float s_sy[NI], s_sx[NI];
    __shared__ int   s_cls[NI];
    __shared__ short s_list[NI];
    __shared__ unsigned s_bal[4];
    __shared__ int   s_off[4];
    __shared__ int   s_cnt;
    __shared__ float4 s_part[TPB];
    __shared__ float  s_wsum[NWARP], s_wcnt[NWARP];

    const int tid  = threadIdx.x;
    const int pix  = tid & (PIX_PER_BLK - 1);
    const int grp  = tid >> 6;            // 0..7
    const int lane = tid & 31;
    const int wrp  = tid >> 5;

    // block pixel span: [p0, p0 + 256)
    const int p0 = blockIdx.x * PIX_PER_BLK * 4;
    const int by0 = p0 / Ww;
    const int by1 = (p0 + PIX_PER_BLK * 4 - 1) / Ww;
    int bxs, bxe;
    if (by0 == by1) { bxs = p0 - by0 * Ww; bxe = bxs + PIX_PER_BLK * 4 - 1; }
    else            { bxs = 0;             bxe = Ww - 1; }   // conservative

    // -------- instance rect prep + block-level overlap flag ------------------
    bool flag = false;
    if (tid < NI) {
        const int n = tid;
        const float4 bb = ((const float4*)bbox)[n];
        const int x0b = (int)floorf(bb.x * 0.25f);
        const int y0b = (int)floorf(bb.y * 0.25f);
        const int x2b = (int)floorf(bb.z * 0.25f);
        const int y2b = (int)floorf(bb.w * 0.25f);
        s_x0[n] = x0b; s_y0[n] = y0b; s_x2[n] = x2b; s_y2[n] = y2b;
        s_sy[n] = (float)MS / (float)(y2b - y0b + 1);
        s_sx[n] = (float)MS / (float)(x2b - x0b + 1);
        const int cx1 = (int)(bb.x * 0.25f);
        const int cy1 = (int)(bb.y * 0.25f);
        const int cx2 = (int)(rintf(bb.z * 0.25f) + 1.0f);
        const int cy2 = (int)(rintf(bb.w * 0.25f) + 1.0f);
        s_cx1[n] = cx1; s_cy1[n] = cy1; s_cx2[n] = cx2; s_cy2[n] = cy2;
        s_cls[n] = cls_idx[n];

        const int rx0 = min(x0b, cx1);
        const int ry0 = min(y0b, cy1);
        const int rx1 = max(x2b, cx2 - 1);
        const int ry1 = max(y2b, cy2 - 1);
        flag = (ry0 <= by1) && (ry1 >= by0) && (rx0 <= bxe) && (rx1 >= bxs);
    }
    const unsigned bal = __ballot_sync(0xffffffffu, flag);
    if (lane == 0 && wrp < 4) s_bal[wrp] = bal;
    __syncthreads();
    if (tid == 0) {
        int off = 0;
        #pragma unroll
        for (int w = 0; w < 4; ++w) { s_off[w] = off; off += __popc(s_bal[w]); }
        s_cnt = off;
    }
    __syncthreads();
    if (flag)
        s_list[s_off[wrp] + __popc(bal & ((1u << lane) - 1u))] = (short)tid;
    __syncthreads();

    // -------- per-(pixel, channel-group) work --------------------------------
    const int qi = blockIdx.x * PIX_PER_BLK + pix;
    const int p  = qi * 4;
    const int y  = p / Ww;
    const int x  = p - y * Ww;

    const float4* sp4 = (const float4*)stuff_logit + qi;
    float4*       op4 = (float4*)out + qi;

    float s0 = 0.f, s1 = 0.f, s2 = 0.f, s3 = 0.f;

    // stuff channels (round-robin c = grp, grp+8, ... < CS): copy + exp
    #pragma unroll 7
    for (int c = grp; c < CS; c += NGRP) {
        const float4 v = sp4[(size_t)c * HW4];
        op4[(size_t)c * HW4] = v;
        s0 += __expf(v.x); s1 += __expf(v.y);
        s2 += __expf(v.z); s3 += __expf(v.w);
    }

    // thing channels in my group (round-robin): tight zero fill + baseline ones
    const int ct_first = CS + ((grp - (CS % NGRP) + NGRP) % NGRP);
    const float4 z4 = make_float4(0.f, 0.f, 0.f, 0.f);
    #pragma unroll 16
    for (int c = ct_first; c < NCH; c += NGRP)
        op4[(size_t)c * HW4] = z4;
    {
        const float ones = (float)((NCH - ct_first + NGRP - 1) / NGRP);  // 16
        s0 += ones; s1 += ones; s2 += ones; s3 += ones;
    }

    // overwrite block-covering instances whose channel falls in my group
    const int m = s_cnt;
    for (int k = 0; k < m; ++k) {
        const int n = s_list[k];
        if (((n + CS) & (NGRP - 1)) != grp) continue;

        const int x0b = s_x0[n], x2b = s_x2[n];
        const int y0b = s_y0[n], y2b = s_y2[n];
        const int cx1 = s_cx1[n], cx2 = s_cx2[n];
        const int cy1 = s_cy1[n], cy2 = s_cy2[n];

        const bool yin_m = (y >= y0b) && (y <= y2b);
        const bool yin_s = (y >= cy1) && (y <  cy2);
        const bool xov_m = yin_m && (x + 3 >= x0b) && (x <= x2b);
        const bool xov_s = yin_s && (x + 3 >= cx1) && (x <  cx2);
        if (!(xov_m || xov_s)) continue;

        const int cls = s_cls[n];
        float ty = 0.f; int i0 = 0, i1 = 0;
        const float* ml = mask_logits + ((size_t)n * CT + cls) * (MS * MS);
        if (xov_m) {
            const float sy = ((float)(y - y0b) + 0.5f) * s_sy[n] - 0.5f;
            const float fy = floorf(sy);
            ty = sy - fy;
            i0 = min(max((int)fy, 0), MS - 1);
            i1 = min(max((int)fy + 1, 0), MS - 1);
        }
        const float* tl = thing_logit + (size_t)cls * HW + p;

        float v[4];
        #pragma unroll
        for (int j = 0; j < 4; ++j) {
            const int xx = x + j;
            float vv = 0.0f;
            if (yin_m && xx >= x0b && xx <= x2b) {
                const float sx = ((float)(xx - x0b) + 0.5f) * s_sx[n] - 0.5f;
                const float fx = floorf(sx);
                const float tx = sx - fx;
                const int j0 = min(max((int)fx, 0), MS - 1);
                const int j1 = min(max((int)fx + 1, 0), MS - 1);
                const float r00 = ml[i0 * MS + j0];
                const float r10 = ml[i1 * MS + j0];
                const float r01 = ml[i0 * MS + j1];
                const float r11 = ml[i1 * MS + j1];
                const float c0 = r00 * (1.0f - ty) + r10 * ty;
                const float c1 = r01 * (1.0f - ty) + r11 * ty;
                vv = c0 * (1.0f - tx) + c1 * tx;
            }
            if (yin_s && xx >= cx1 && xx < cx2) vv += tl[j];
            v[j] = vv;
        }
        s0 += __expf(v[0]) - 1.0f;
        s1 += __expf(v[1]) - 1.0f;
        s2 += __expf(v[2]) - 1.0f;
        s3 += __expf(v[3]) - 1.0f;
        op4[(size_t)(n + CS) * HW4] = make_float4(v[0], v[1], v[2], v[3]);
    }

    // -------- combine NGRP partials per pixel --------------------------------
    s_part[tid] = make_float4(s0, s1, s2, s3);
    __syncthreads();   // block-scope visibility of all this block's stores

    float contrib = 0.0f, cnt = 0.0f;

    if (grp == 0) {    // tid < 64
        float t0s = 0.f, t1s = 0.f, t2s = 0.f, t3s = 0.f;
        #pragma unroll
        for (int g = 0; g < NGRP; ++g) {
            const float4 pp = s_part[pix + g * PIX_PER_BLK];
            t0s += pp.x; t1s += pp.y; t2s += pp.z; t3s += pp.w;
        }

        const int* gr = gt + (size_t)(y * 4) * HG + (size_t)x * 4;
        const int g0 = gr[0], g1 = gr[4], g2 = gr[8], g3 = gr[12];

        const int t0 = min(max(g0, 0), NCH - 1);
        const int t1 = min(max(g1, 0), NCH - 1);
        const int t2 = min(max(g2, 0), NCH - 1);
        const int t3 = min(max(g3, 0), NCH - 1);
        const float tv0 = out[(size_t)t0 * HW + p + 0];
        const float tv1 = out[(size_t)t1 * HW + p + 1];
        const float tv2 = out[(size_t)t2 * HW + p + 2];
        const float tv3 = out[(size_t)t3 * HW + p + 3];

        if (g0 != IGNORE_LBL) { contrib += __logf(t0s) - tv0; cnt += 1.f; }
        if (g1 != IGNORE_LBL) { contrib += __logf(t1s) - tv1; cnt += 1.f; }
        if (g2 != IGNORE_LBL) { contrib += __logf(t2s) - tv2; cnt += 1.f; }
        if (g3 != IGNORE_LBL) { contrib += __logf(t3s) - tv3; cnt += 1.f; }
    }

    // -------- deterministic shuffle-tree block reduction ---------------------
    #pragma unroll
    for (int off = 16; off > 0; off >>= 1) {
        contrib += __shfl_down_sync(0xffffffffu, contrib, off);
        cnt     += __shfl_down_sync(0xffffffffu, cnt,     off);
    }
    if (lane == 0) { s_wsum[wrp] = contrib; s_wcnt[wrp] = cnt; }
    __syncthreads();

    __shared__ bool is_last;
    if (wrp == 0) {
        float ws = (lane < NWARP) ? s_wsum[lane] : 0.f;
        float wc = (lane < NWARP) ? s_wcnt[lane] : 0.f;
        #pragma unroll
        for (int off = 8; off > 0; off >>= 1) {
            ws += __shfl_down_sync(0xffffffffu, ws, off);
            wc += __shfl_down_sync(0xffffffffu, wc, off);
        }
        if (lane == 0) {
            g_partial[blockIdx.x] = ws;
            g_count[blockIdx.x]   = wc;
            __threadfence();
            const unsigned old = atomicAdd(&g_ctr, 1u);
            is_last = (old == NBLK - 1);
            if (is_last) g_ctr = 0;      // reset for graph replay
        }
    }
    __syncthreads();

    if (is_last) {
        __shared__ double s_dsum[NWARP], s_dcnt[NWARP];
        double s = 0.0, c = 0.0;
        for (int i = tid; i < NBLK; i += TPB) {
            s += (double)g_partial[i];
            c += (double)g_count[i];
        }
        #pragma unroll
        for (int off = 16; off > 0; off >>= 1) {
            s += __shfl_down_sync(0xffffffffu, s, off);
            c += __shfl_down_sync(0xffffffffu, c, off);
        }
        if (lane == 0) { s_dsum[wrp] = s; s_dcnt[wrp] = c; }
        __syncthreads();
        if (wrp == 0) {
            double ds = (lane < NWARP) ? s_dsum[lane] : 0.0;
            double dc = (lane < NWARP) ? s_dcnt[lane] : 0.0;
            #pragma unroll
            for (int off = 8; off > 0; off >>= 1) {
                ds += __shfl_down_sync(0xffffffffu, ds, off);
                dc += __shfl_down_sync(0xffffffffu, dc, off);
            }
            if (lane == 0) *loss_out = (float)(ds / fmax(dc, 1.0));
        }
    }
}

// ---------------------------------------------------------------------------
extern "C" void kernel_launch(void* const* d_in, const int* in_sizes, int n_in,
                              void* d_out, int out_size)
{
    const float* mask_logits = (const float*)d_in[0];
    const float* stuff_logit = (const float*)d_in[1];
    const float* thing_logit = (const float*)d_in[2];
    const float* bbox        = (const float*)d_in[3];
    const int*   cls_idx     = (const int*)  d_in[4];
    const int*   gt          = (const int*)  d_in[5];

    float* out = (float*)d_out;

    fused_kernel<<<NBLK, TPB>>>(mask_logits, stuff_logit, thing_logit,
                                bbox, cls_idx, gt, out,
                                out + (size_t)out_size - 1);
}